// round 7
// baseline (speedup 1.0000x reference)
#include <cuda_runtime.h>
#include <math.h>

#define HGT   64
#define WID   64
#define CH    256
#define BATCH 4
#define HW    (HGT*WID)
#define RAD   3
#define NK    49
#define PXB   32          // pixels per logits block (half row)
#define NCB   (PXB+6)     // 38 neighborhood columns
#define X2ROWS (7*NCB)    // 266
#define CHUNK 16
#define STR   20          // smem row stride for x2/u rows (16 ch + pad)
#define X1STR 36          // x1 tile stride: 32 px + 4 pad
#define WSTR  52

// scratch
__device__ float g_u[BATCH*HW*CH];   // u = (w1^T w2) x, pixel-major [B][HW][C]
__device__ float g_v[BATCH*HW*CH];   // v = w3 x,        pixel-major
__device__ float g_M[CH*CH];         // M = w1^T w2, row-major [o][c]

// ---------------- f32x2 packed helpers ----------------
__device__ __forceinline__ void fma2(unsigned long long& d,
                                     unsigned long long a,
                                     unsigned long long b) {
    asm("fma.rn.f32x2 %0, %1, %2, %0;" : "+l"(d) : "l"(a), "l"(b));
}
__device__ __forceinline__ unsigned long long dup2(float v) {
    unsigned long long d; unsigned r = __float_as_uint(v);
    asm("mov.b64 %0, {%1, %2};" : "=l"(d) : "r"(r), "r"(r));
    return d;
}
__device__ __forceinline__ unsigned long long pack2(float lo, float hi) {
    unsigned long long d;
    asm("mov.b64 %0, {%1, %2};" : "=l"(d) : "r"(__float_as_uint(lo)), "r"(__float_as_uint(hi)));
    return d;
}
__device__ __forceinline__ float2 unpk(unsigned long long v) {
    unsigned lo, hi;
    asm("mov.b64 {%0, %1}, %2;" : "=r"(lo), "=r"(hi) : "l"(v));
    return make_float2(__uint_as_float(lo), __uint_as_float(hi));
}

// ---------------------------------------------------------------------------
// M = w1^T w2:  M[i][j] = sum_t w1[t][i] * w2[t][j].  grid (2,2), 128x128 tile.
// Both operands staged directly (k-major rows), FFMA2 microtile.
// ---------------------------------------------------------------------------
__global__ __launch_bounds__(256) void mmul_kernel(
    const float* __restrict__ w1, const float* __restrict__ w2)
{
    const int i0 = blockIdx.x * 128;
    const int j0 = blockIdx.y * 128;

    __shared__ float As[2][8][128];
    __shared__ float Bs[2][8][128];

    const int tid = threadIdx.x;
    const int tx  = tid & 15;
    const int ty  = tid >> 4;
    const int kr  = tid >> 5;           // 0..7
    const int c4  = (tid & 31) << 2;    // 0..124

    const float* Ap = w1 + (size_t)kr * CH + i0 + c4;
    const float* Bp = w2 + (size_t)kr * CH + j0 + c4;

    float4 ra = *(const float4*)Ap;
    float4 rb = *(const float4*)Bp;
    *(float4*)(&As[0][kr][c4]) = ra;
    *(float4*)(&Bs[0][kr][c4]) = rb;
    __syncthreads();

    unsigned long long acc2[4][8];
#pragma unroll
    for (int i = 0; i < 4; i++)
#pragma unroll
        for (int j = 0; j < 8; j++) acc2[i][j] = 0ULL;

#pragma unroll 2
    for (int kt = 0; kt < 32; kt++) {
        const int cur = kt & 1;
        if (kt < 31) {
            ra = *(const float4*)(Ap + (size_t)(kt + 1) * 8 * CH);
            rb = *(const float4*)(Bp + (size_t)(kt + 1) * 8 * CH);
        }
#pragma unroll
        for (int k = 0; k < 8; k++) {
            ulonglong2 a01 = *(const ulonglong2*)(&As[cur][k][ty * 4]);
            ulonglong2 a23 = *(const ulonglong2*)(&As[cur][k][64 + ty * 4]);
            float4 bv0 = *(const float4*)(&Bs[cur][k][tx * 4]);
            float4 bv1 = *(const float4*)(&Bs[cur][k][64 + tx * 4]);
            unsigned long long av[4] = { a01.x, a01.y, a23.x, a23.y };
            unsigned long long bd[8];
            bd[0] = dup2(bv0.x); bd[1] = dup2(bv0.y);
            bd[2] = dup2(bv0.z); bd[3] = dup2(bv0.w);
            bd[4] = dup2(bv1.x); bd[5] = dup2(bv1.y);
            bd[6] = dup2(bv1.z); bd[7] = dup2(bv1.w);
#pragma unroll
            for (int i2 = 0; i2 < 4; i2++)
#pragma unroll
                for (int j = 0; j < 8; j++)
                    fma2(acc2[i2][j], av[i2], bd[j]);
        }
        if (kt < 31) {
            const int nxt = cur ^ 1;
            *(float4*)(&As[nxt][kr][c4]) = ra;
            *(float4*)(&Bs[nxt][kr][c4]) = rb;
            __syncthreads();
        }
    }

#pragma unroll
    for (int i2 = 0; i2 < 4; i2++) {
        const int irow = i0 + ((i2 < 2) ? (ty * 4 + 2 * i2)
                                        : (64 + ty * 4 + 2 * (i2 - 2)));
        float lo[8], hi[8];
#pragma unroll
        for (int j = 0; j < 8; j++) {
            float2 t = unpk(acc2[i2][j]);
            lo[j] = t.x; hi[j] = t.y;
        }
        float* yl = g_M + (size_t)irow * CH + j0;
        *(float4*)(yl + tx * 4)      = make_float4(lo[0], lo[1], lo[2], lo[3]);
        *(float4*)(yl + 64 + tx * 4) = make_float4(lo[4], lo[5], lo[6], lo[7]);
        float* yh = yl + CH;
        *(float4*)(yh + tx * 4)      = make_float4(hi[0], hi[1], hi[2], hi[3]);
        *(float4*)(yh + 64 + tx * 4) = make_float4(hi[4], hi[5], hi[6], hi[7]);
    }
}

// ---------------------------------------------------------------------------
// GEMM: Yt[b][p][o] = sum_c W[o][c] X[b][c][p], W in {g_M -> g_u, w3 -> g_v}
// 128x128 tile, BK=8, double-buffered, FFMA2 microtile.
// ---------------------------------------------------------------------------
__global__ __launch_bounds__(256) void gemm_kernel(
    const float* __restrict__ x, const float* __restrict__ w3)
{
    const int z    = blockIdx.z;        // 0..7
    const int b    = z >> 1;
    const int wsel = z & 1;
    const float* W = (wsel == 0) ? g_M : w3;
    float* Y = ((wsel == 0) ? g_u : g_v) + (size_t)b * HW * CH;
    const float* X = x + (size_t)b * CH * HW;

    const int p0 = blockIdx.x * 128;
    const int o0 = blockIdx.y * 128;

    __shared__ float As[2][8][128];
    __shared__ float Bs[2][8][128];

    const int tid = threadIdx.x;
    const int tx  = tid & 15;
    const int ty  = tid >> 4;

    const int a_cr = tid >> 5;
    const int a_p4 = (tid & 31) << 2;
    const int b_o  = tid >> 1;
    const int b_c4 = (tid & 1) << 2;

    const float* Xa = X + (size_t)a_cr * HW + p0 + a_p4;
    const float* Wb = W + (size_t)(o0 + b_o) * CH + b_c4;

    float4 ra = *(const float4*)Xa;
    float4 rb = *(const float4*)Wb;
    *(float4*)(&As[0][a_cr][a_p4]) = ra;
    Bs[0][b_c4 + 0][b_o] = rb.x;
    Bs[0][b_c4 + 1][b_o] = rb.y;
    Bs[0][b_c4 + 2][b_o] = rb.z;
    Bs[0][b_c4 + 3][b_o] = rb.w;
    __syncthreads();

    unsigned long long acc2[4][8];
#pragma unroll
    for (int i = 0; i < 4; i++)
#pragma unroll
        for (int j = 0; j < 8; j++) acc2[i][j] = 0ULL;

#pragma unroll 2
    for (int kt = 0; kt < 32; kt++) {
        const int cur = kt & 1;
        if (kt < 31) {
            ra = *(const float4*)(Xa + (size_t)(kt + 1) * 8 * HW);
            rb = *(const float4*)(Wb + (kt + 1) * 8);
        }
#pragma unroll
        for (int k = 0; k < 8; k++) {
            ulonglong2 a01 = *(const ulonglong2*)(&As[cur][k][ty * 4]);
            ulonglong2 a23 = *(const ulonglong2*)(&As[cur][k][64 + ty * 4]);
            float4 bv0 = *(const float4*)(&Bs[cur][k][tx * 4]);
            float4 bv1 = *(const float4*)(&Bs[cur][k][64 + tx * 4]);
            unsigned long long av[4] = { a01.x, a01.y, a23.x, a23.y };
            unsigned long long bd[8];
            bd[0] = dup2(bv0.x); bd[1] = dup2(bv0.y);
            bd[2] = dup2(bv0.z); bd[3] = dup2(bv0.w);
            bd[4] = dup2(bv1.x); bd[5] = dup2(bv1.y);
            bd[6] = dup2(bv1.z); bd[7] = dup2(bv1.w);
#pragma unroll
            for (int i2 = 0; i2 < 4; i2++)
#pragma unroll
                for (int j = 0; j < 8; j++)
                    fma2(acc2[i2][j], av[i2], bd[j]);
        }
        if (kt < 31) {
            const int nxt = cur ^ 1;
            *(float4*)(&As[nxt][a_cr][a_p4]) = ra;
            Bs[nxt][b_c4 + 0][b_o] = rb.x;
            Bs[nxt][b_c4 + 1][b_o] = rb.y;
            Bs[nxt][b_c4 + 2][b_o] = rb.z;
            Bs[nxt][b_c4 + 3][b_o] = rb.w;
            __syncthreads();
        }
    }

#pragma unroll
    for (int i2 = 0; i2 < 4; i2++) {
        const int prow = p0 + ((i2 < 2) ? (ty * 4 + 2 * i2)
                                        : (64 + ty * 4 + 2 * (i2 - 2)));
        float lo[8], hi[8];
#pragma unroll
        for (int j = 0; j < 8; j++) {
            float2 t = unpk(acc2[i2][j]);
            lo[j] = t.x; hi[j] = t.y;
        }
        float* yl = Y + (size_t)prow * CH + o0;
        *(float4*)(yl + tx * 4)      = make_float4(lo[0], lo[1], lo[2], lo[3]);
        *(float4*)(yl + 64 + tx * 4) = make_float4(lo[4], lo[5], lo[6], lo[7]);
        float* yh = yl + CH;
        *(float4*)(yh + tx * 4)      = make_float4(hi[0], hi[1], hi[2], hi[3]);
        *(float4*)(yh + 64 + tx * 4) = make_float4(hi[4], hi[5], hi[6], hi[7]);
    }
}

// ---------------------------------------------------------------------------
// Attention: block = (b, h, half-row of 32 px). 256 threads.
// Phase 1: logits(p,n) = x(p) . u(n); x staged transposed from channel-major,
//          u rows staged pixel-major; FFMA2 inner; reg double-buffered staging.
// Phase 2: thread = channel; two passes of 16 register accumulators (R5).
// smem floats: ws[32*52]=1664 | x1s[16][36]=576 | x2s[266*20]=5320 = 7560
//              outS[256*20]=5120 aliases x1s+x2s.
// ---------------------------------------------------------------------------
#define WS_OFF   0
#define X1_OFF   1664
#define X2_OFF   (1664 + CHUNK*X1STR)               // 2240
#define OUTS_OFF 1664
#define SMEM_FLOATS (1664 + CHUNK*X1STR + X2ROWS*STR)   // 7560
#define NUNITS   (128 + X2ROWS*4)                   // 1192 float4 units/chunk

__global__ __launch_bounds__(256) void attn_kernel(
    const float* __restrict__ x, float* __restrict__ out)
{
    __shared__ float smem[SMEM_FLOATS];
    float* ws   = smem + WS_OFF;
    float* outS = smem + OUTS_OFF;

    const int blk  = blockIdx.x;          // b*128 + h*2 + half
    const int b    = blk >> 7;
    const int h    = (blk >> 1) & 63;
    const int half = blk & 1;
    const int px0  = half * PXB;
    const int tid  = threadIdx.x;

    const int px   = tid >> 3;            // 0..31
    const int part = tid & 7;             // 0..7

    const size_t bbase = (size_t)b * HW;

    // ---- staging plan: 5 float4 units per thread ----
    const float* gp[5];
    int so[5], cs[5];
#pragma unroll
    for (int it = 0; it < 5; it++) {
        int unit = tid + it * 256;
        gp[it] = 0; so[it] = -1; cs[it] = 0;
        if (unit < 128) {
            // x tile: channel-major read, 16 ch x 32 px
            int c  = unit >> 3;            // 0..15
            int p4 = (unit & 7) << 2;      // 0..28
            gp[it] = x + ((size_t)b * CH + c) * HW + (size_t)h * WID + px0 + p4;
            so[it] = X1_OFF + c * X1STR + p4;
            cs[it] = CHUNK * HW;
        } else if (unit < NUNITS) {
            int u   = unit - 128;
            int row = u >> 2;
            int c4  = (u & 3) << 2;
            int dh  = row / NCB;
            int col = row - dh * NCB;
            int hh  = h + dh - RAD;
            int gw  = px0 + col - RAD;
            so[it] = X2_OFF + row * STR + c4;
            cs[it] = CHUNK;
            if (hh >= 0 && hh < HGT && gw >= 0 && gw < WID)
                gp[it] = g_u + (bbase + (size_t)hh * WID + gw) * CH + c4;
        }
    }

    unsigned long long acc2[7];
    int nbrow[7];
#pragma unroll
    for (int j = 0; j < 7; j++) {
        acc2[j] = 0ULL;
        int k  = part + 8 * j;
        int kk = (k < NK) ? k : 0;
        int dh = kk / 7, dw = kk - dh * 7;
        nbrow[j] = X2_OFF + (dh * NCB + px + dw) * STR;
    }

    // prologue: chunk 0 into registers
    float4 rg[5];
#pragma unroll
    for (int it = 0; it < 5; it++) {
        rg[it] = make_float4(0.f, 0.f, 0.f, 0.f);
        if (so[it] >= 0 && gp[it]) rg[it] = *(const float4*)(gp[it]);
    }

    for (int ch = 0; ch < CH / CHUNK; ch++) {
#pragma unroll
        for (int it = 0; it < 5; it++)
            if (so[it] >= 0) *(float4*)(smem + so[it]) = rg[it];
        __syncthreads();

        if (ch + 1 < CH / CHUNK) {
#pragma unroll
            for (int it = 0; it < 5; it++) {
                rg[it] = make_float4(0.f, 0.f, 0.f, 0.f);
                if (so[it] >= 0 && gp[it]) {
                    gp[it] += cs[it];
                    rg[it] = *(const float4*)(gp[it]);
                }
            }
        }

        // q pairs for this chunk (broadcast scalar LDS, conflict-free)
        unsigned long long qp[8];
#pragma unroll
        for (int i = 0; i < 8; i++)
            qp[i] = pack2(smem[X1_OFF + (2 * i) * X1STR + px],
                          smem[X1_OFF + (2 * i + 1) * X1STR + px]);

#pragma unroll
        for (int c4 = 0; c4 < CHUNK; c4 += 4) {
#pragma unroll
            for (int j = 0; j < 7; j++) {
                ulonglong2 k2 = *(const ulonglong2*)(smem + nbrow[j] + c4);
                fma2(acc2[j], qp[c4 >> 1], k2.x);
                fma2(acc2[j], qp[(c4 >> 1) + 1], k2.y);
            }
        }
        __syncthreads();
    }

    float acc[7];
#pragma unroll
    for (int j = 0; j < 7; j++) {
        float2 t = unpk(acc2[j]);
        acc[j] = t.x + t.y;
    }

    // softmax across the 8-thread group owning pixel px
    float m = -1e30f;
#pragma unroll
    for (int j = 0; j < 7; j++)
        if (part + 8 * j < NK) m = fmaxf(m, acc[j]);
    m = fmaxf(m, __shfl_xor_sync(0xffffffffu, m, 1));
    m = fmaxf(m, __shfl_xor_sync(0xffffffffu, m, 2));
    m = fmaxf(m, __shfl_xor_sync(0xffffffffu, m, 4));

    float e[7];
    float s = 0.f;
#pragma unroll
    for (int j = 0; j < 7; j++) {
        int k = part + 8 * j;
        e[j] = (k < NK) ? __expf(acc[j] - m) : 0.f;
        s += e[j];
    }
    s += __shfl_xor_sync(0xffffffffu, s, 1);
    s += __shfl_xor_sync(0xffffffffu, s, 2);
    s += __shfl_xor_sync(0xffffffffu, s, 4);
    float inv = 1.f / s;
#pragma unroll
    for (int j = 0; j < 7; j++) {
        int k = part + 8 * j;
        if (k < NK) ws[px * WSTR + k] = e[j] * inv;
    }
    __syncthreads();

    // ---- Phase 2: thread = channel; two passes of 16 pixels ----
    const int c = tid;
#pragma unroll 1
    for (int hv = 0; hv < 2; hv++) {
        const int p0h = px0 + hv * 16;
        const int pl0 = hv * 16;

        float oacc[16];
#pragma unroll
        for (int i = 0; i < 16; i++) oacc[i] = 0.f;

        for (int dh = 0; dh < 7; dh++) {
            int hh = h + dh - RAD;
            if (hh < 0 || hh >= HGT) continue;          // uniform branch
            const float* vrow = g_v + (bbase + (size_t)hh * WID) * CH + c;
            const float* wsp  = ws + pl0 * WSTR + dh * 7;
#pragma unroll
            for (int wg = 0; wg < 22; wg++) {           // 16 + 6 cols
                int gw2 = p0h + wg - RAD;
                float vv = (gw2 >= 0 && gw2 < WID) ? vrow[(size_t)gw2 * CH] : 0.f;
#pragma unroll
                for (int dw = 0; dw < 7; dw++) {
                    int pl = wg - dw;
                    if (pl >= 0 && pl < 16)
                        oacc[pl] = fmaf(wsp[pl * WSTR + dw], vv, oacc[pl]);
                }
            }
        }

        // transpose through smem for coalesced stores
#pragma unroll
        for (int i = 0; i < 16; i++) outS[c * STR + i] = oacc[i];
        __syncthreads();

#pragma unroll
        for (int r4 = 0; r4 < 4; r4++) {
            int idx = tid + r4 * 256;
            int cch = idx >> 2;
            int w4  = (idx & 3) << 2;
            float4 v = *(const float4*)(outS + cch * STR + w4);
            *(float4*)(out + ((size_t)(b * CH + cch) * HGT + h) * WID + p0h + w4) = v;
        }
        __syncthreads();
    }
}

// ---------------------------------------------------------------------------
extern "C" void kernel_launch(void* const* d_in, const int* in_sizes, int n_in,
                              void* d_out, int out_size)
{
    const float* x  = (const float*)d_in[0];
    const float* w1 = (const float*)d_in[1];
    const float* w2 = (const float*)d_in[2];
    const float* w3 = (const float*)d_in[3];
    float* out = (float*)d_out;
    (void)in_sizes; (void)n_in; (void)out_size;

    mmul_kernel<<<dim3(2, 2), 256>>>(w1, w2);

    dim3 ggrid(HW / 128, CH / 128, BATCH * 2);
    gemm_kernel<<<ggrid, 256>>>(x, w3);

    attn_kernel<<<BATCH * HGT * 2, 256>>>(x, out);
}

// round 9
// speedup vs baseline: 1.6361x; 1.6361x over previous
#include <cuda_runtime.h>
#include <math.h>

#define HGT   64
#define WID   64
#define CH    256
#define BATCH 4
#define HW    (HGT*WID)
#define RAD   3
#define NK    49
#define PXB   32          // pixels per attn block (half row)
#define NCB   (PXB+6)     // 38 neighborhood columns
#define X2ROWS (7*NCB)    // 266
#define CHUNK 16
#define STR   20          // smem row stride (floats) for 16-ch chunk
#define WSTR  52

// Pixel-major scratch: [B][HW][C]
__device__ float g_q[BATCH*HW*CH];   // x transposed to pixel-major (query = x)
__device__ float g_u[BATCH*HW*CH];   // u = (w1^T w2) x   (key side)
__device__ float g_v[BATCH*HW*CH];   // v = w3 x
__device__ float g_M[CH*CH];         // M[i][j] = sum_t w1[t][i] w2[t][j]

// ---------------- f32x2 packed helpers ----------------
__device__ __forceinline__ void fma2(unsigned long long& d,
                                     unsigned long long a,
                                     unsigned long long b) {
    asm("fma.rn.f32x2 %0, %1, %2, %0;" : "+l"(d) : "l"(a), "l"(b));
}
__device__ __forceinline__ unsigned long long dup2(float v) {
    unsigned long long d; unsigned r = __float_as_uint(v);
    asm("mov.b64 %0, {%1, %2};" : "=l"(d) : "r"(r), "r"(r));
    return d;
}
__device__ __forceinline__ float2 unpk(unsigned long long v) {
    unsigned lo, hi;
    asm("mov.b64 {%0, %1}, %2;" : "=r"(lo), "=r"(hi) : "l"(v));
    return make_float2(__uint_as_float(lo), __uint_as_float(hi));
}

// ---------------------------------------------------------------------------
// pre_kernel: blocks 0..255 transpose x -> g_q (pixel-major);
//             blocks 256..271 compute g_M = w1^T w2 (64x64 tiles).
// One wave; the two jobs run concurrently.
// ---------------------------------------------------------------------------
__global__ __launch_bounds__(256) void pre_kernel(
    const float* __restrict__ x,
    const float* __restrict__ w1,
    const float* __restrict__ w2)
{
    __shared__ float sm[64 * 65];     // transpose tile; mmul uses first 2048
    const int blk = blockIdx.x;
    const int tid = threadIdx.x;

    if (blk < 256) {
        // ---- transpose one (b,h) row: 64 px x 256 ch ----
        const int b = blk >> 6, h = blk & 63;
        const float* xb = x + (size_t)b * CH * HW + (size_t)h * WID;
        float* qb = g_q + ((size_t)b * HW + (size_t)h * WID) * CH;

        for (int c0 = 0; c0 < CH; c0 += 64) {
#pragma unroll
            for (int r = 0; r < 4; r++) {
                int u  = tid + r * 256;        // 0..1023
                int c  = u >> 4;               // 0..63
                int p4 = (u & 15) << 2;        // 0..60
                float4 v = *(const float4*)(xb + (size_t)(c0 + c) * HW + p4);
                sm[c * 65 + p4 + 0] = v.x;
                sm[c * 65 + p4 + 1] = v.y;
                sm[c * 65 + p4 + 2] = v.z;
                sm[c * 65 + p4 + 3] = v.w;
            }
            __syncthreads();
#pragma unroll
            for (int r = 0; r < 4; r++) {
                int u  = tid + r * 256;
                int p  = u >> 4;               // 0..63
                int c4 = (u & 15) << 2;        // 0..60
                float4 v = make_float4(sm[(c4 + 0) * 65 + p],
                                       sm[(c4 + 1) * 65 + p],
                                       sm[(c4 + 2) * 65 + p],
                                       sm[(c4 + 3) * 65 + p]);
                *(float4*)(qb + (size_t)p * CH + c0 + c4) = v;
            }
            __syncthreads();
        }
    } else {
        // ---- mmul: 64x64 tile of M = w1^T w2 ----
        const int t  = blk - 256;              // 0..15
        const int i0 = (t & 3) * 64;
        const int j0 = (t >> 2) * 64;
        float* As = sm;
        float* Bs = sm + 16 * 64;

        const int ti = (tid & 15) << 2;
        const int tj = (tid >> 4) << 2;
        const int tr = tid >> 4;               // 0..15
        const int i4 = (tid & 15) << 2;

        float acc[4][4];
#pragma unroll
        for (int a = 0; a < 4; a++)
#pragma unroll
            for (int bb = 0; bb < 4; bb++) acc[a][bb] = 0.f;

        for (int k0 = 0; k0 < CH; k0 += 16) {
            *(float4*)(As + tr * 64 + i4) =
                *(const float4*)(w1 + (size_t)(k0 + tr) * CH + i0 + i4);
            *(float4*)(Bs + tr * 64 + i4) =
                *(const float4*)(w2 + (size_t)(k0 + tr) * CH + j0 + i4);
            __syncthreads();
#pragma unroll
            for (int k = 0; k < 16; k++) {
                float4 a = *(const float4*)(As + k * 64 + ti);
                float4 bv = *(const float4*)(Bs + k * 64 + tj);
                float av[4] = { a.x, a.y, a.z, a.w };
                float bw[4] = { bv.x, bv.y, bv.z, bv.w };
#pragma unroll
                for (int ii = 0; ii < 4; ii++)
#pragma unroll
                    for (int jj = 0; jj < 4; jj++)
                        acc[ii][jj] = fmaf(av[ii], bw[jj], acc[ii][jj]);
            }
            __syncthreads();
        }
#pragma unroll
        for (int ii = 0; ii < 4; ii++)
            *(float4*)(g_M + (size_t)(i0 + ti + ii) * CH + j0 + tj) =
                make_float4(acc[ii][0], acc[ii][1], acc[ii][2], acc[ii][3]);
    }
}

// ---------------------------------------------------------------------------
// GEMM: Yt[b][p][o] = sum_c W[o][c] X[b][c][p], W in {g_M -> g_u, w3 -> g_v}
// 128x128 tile, BK=8, double-buffered, FFMA2 microtile.  (R6 kernel, 2/3 work)
// ---------------------------------------------------------------------------
__global__ __launch_bounds__(256) void gemm_kernel(
    const float* __restrict__ x, const float* __restrict__ w3)
{
    const int z    = blockIdx.z;        // 0..7
    const int b    = z >> 1;
    const int wsel = z & 1;
    const float* W = (wsel == 0) ? g_M : w3;
    float* Y = ((wsel == 0) ? g_u : g_v) + (size_t)b * HW * CH;
    const float* X = x + (size_t)b * CH * HW;

    const int p0 = blockIdx.x * 128;
    const int o0 = blockIdx.y * 128;

    __shared__ float As[2][8][128];
    __shared__ float Bs[2][8][128];

    const int tid = threadIdx.x;
    const int tx  = tid & 15;
    const int ty  = tid >> 4;

    const int a_cr = tid >> 5;
    const int a_p4 = (tid & 31) << 2;
    const int b_o  = tid >> 1;
    const int b_c4 = (tid & 1) << 2;

    const float* Xa = X + (size_t)a_cr * HW + p0 + a_p4;
    const float* Wb = W + (size_t)(o0 + b_o) * CH + b_c4;

    float4 ra = *(const float4*)Xa;
    float4 rb = *(const float4*)Wb;
    *(float4*)(&As[0][a_cr][a_p4]) = ra;
    Bs[0][b_c4 + 0][b_o] = rb.x;
    Bs[0][b_c4 + 1][b_o] = rb.y;
    Bs[0][b_c4 + 2][b_o] = rb.z;
    Bs[0][b_c4 + 3][b_o] = rb.w;
    __syncthreads();

    unsigned long long acc2[4][8];
#pragma unroll
    for (int i = 0; i < 4; i++)
#pragma unroll
        for (int j = 0; j < 8; j++) acc2[i][j] = 0ULL;

#pragma unroll 2
    for (int kt = 0; kt < 32; kt++) {
        const int cur = kt & 1;
        if (kt < 31) {
            ra = *(const float4*)(Xa + (size_t)(kt + 1) * 8 * HW);
            rb = *(const float4*)(Wb + (kt + 1) * 8);
        }
#pragma unroll
        for (int k = 0; k < 8; k++) {
            ulonglong2 a01 = *(const ulonglong2*)(&As[cur][k][ty * 4]);
            ulonglong2 a23 = *(const ulonglong2*)(&As[cur][k][64 + ty * 4]);
            float4 bv0 = *(const float4*)(&Bs[cur][k][tx * 4]);
            float4 bv1 = *(const float4*)(&Bs[cur][k][64 + tx * 4]);
            unsigned long long av[4] = { a01.x, a01.y, a23.x, a23.y };
            unsigned long long bd[8];
            bd[0] = dup2(bv0.x); bd[1] = dup2(bv0.y);
            bd[2] = dup2(bv0.z); bd[3] = dup2(bv0.w);
            bd[4] = dup2(bv1.x); bd[5] = dup2(bv1.y);
            bd[6] = dup2(bv1.z); bd[7] = dup2(bv1.w);
#pragma unroll
            for (int i2 = 0; i2 < 4; i2++)
#pragma unroll
                for (int j = 0; j < 8; j++)
                    fma2(acc2[i2][j], av[i2], bd[j]);
        }
        if (kt < 31) {
            const int nxt = cur ^ 1;
            *(float4*)(&As[nxt][a_cr][a_p4]) = ra;
            Bs[nxt][b_c4 + 0][b_o] = rb.x;
            Bs[nxt][b_c4 + 1][b_o] = rb.y;
            Bs[nxt][b_c4 + 2][b_o] = rb.z;
            Bs[nxt][b_c4 + 3][b_o] = rb.w;
            __syncthreads();
        }
    }

#pragma unroll
    for (int i2 = 0; i2 < 4; i2++) {
        const int prow = p0 + ((i2 < 2) ? (ty * 4 + 2 * i2)
                                        : (64 + ty * 4 + 2 * (i2 - 2)));
        float lo[8], hi[8];
#pragma unroll
        for (int j = 0; j < 8; j++) {
            float2 t = unpk(acc2[i2][j]);
            lo[j] = t.x; hi[j] = t.y;
        }
        float* yl = Y + (size_t)prow * CH + o0;
        *(float4*)(yl + tx * 4)      = make_float4(lo[0], lo[1], lo[2], lo[3]);
        *(float4*)(yl + 64 + tx * 4) = make_float4(lo[4], lo[5], lo[6], lo[7]);
        float* yh = yl + CH;
        *(float4*)(yh + tx * 4)      = make_float4(hi[0], hi[1], hi[2], hi[3]);
        *(float4*)(yh + 64 + tx * 4) = make_float4(hi[4], hi[5], hi[6], hi[7]);
    }
}

// ---------------------------------------------------------------------------
// Attention (R5 kernel verbatim; q := g_q (= x pixel-major), k := g_u).
// Block = (b, h, half-row of 32 px). 256 threads, 30.5KB static smem.
// ---------------------------------------------------------------------------
#define WS_OFF   0
#define X1_OFF   1664
#define X2_OFF   (1664 + PXB*STR)       // 2304
#define OUTS_OFF 1664
#define SMEM_FLOATS (1664 + PXB*STR + X2ROWS*STR)   // 7624
#define NUNITS   (PXB*4 + X2ROWS*4)     // 1192 float4 staging units per chunk

__global__ __launch_bounds__(256) void attn_kernel(float* __restrict__ out)
{
    __shared__ float smem[SMEM_FLOATS];
    float* ws   = smem + WS_OFF;
    float* outS = smem + OUTS_OFF;

    const int blk  = blockIdx.x;          // b*128 + h*2 + half
    const int b    = blk >> 7;
    const int h    = (blk >> 1) & 63;
    const int half = blk & 1;
    const int px0  = half * PXB;
    const int tid  = threadIdx.x;

    const int px   = tid >> 3;            // 0..31
    const int part = tid & 7;             // 0..7

    const size_t bbase = (size_t)b * HW;

    // ---- staging plan: 5 float4 units per thread, computed once ----
    const float* gp[5];
    int so[5];
#pragma unroll
    for (int it = 0; it < 5; it++) {
        int unit = tid + it * 256;
        gp[it] = 0; so[it] = -1;
        if (unit < PXB * 4) {
            int p  = unit >> 2;
            int c4 = (unit & 3) << 2;
            gp[it] = g_q + (bbase + (size_t)h * WID + px0 + p) * CH + c4;
            so[it] = X1_OFF + p * STR + c4;
        } else if (unit < NUNITS) {
            int u   = unit - PXB * 4;
            int row = u >> 2;
            int c4  = (u & 3) << 2;
            int dh  = row / NCB;
            int col = row - dh * NCB;
            int hh  = h + dh - RAD;
            int gw  = px0 + col - RAD;
            so[it] = X2_OFF + row * STR + c4;
            if (hh >= 0 && hh < HGT && gw >= 0 && gw < WID)
                gp[it] = g_u + (bbase + (size_t)hh * WID + gw) * CH + c4;
        }
    }

    // ---- per-thread logit rows ----
    float acc[7];
    int   nbrow[7];
#pragma unroll
    for (int j = 0; j < 7; j++) {
        acc[j] = 0.f;
        int k  = part + 8 * j;
        int kk = (k < NK) ? k : 0;
        int dh = kk / 7, dw = kk - dh * 7;
        nbrow[j] = X2_OFF + (dh * NCB + px + dw) * STR;
    }

    // ---- prologue: load chunk 0 into registers ----
    float4 rg[5];
#pragma unroll
    for (int it = 0; it < 5; it++) {
        rg[it] = make_float4(0.f, 0.f, 0.f, 0.f);
        if (so[it] >= 0 && gp[it]) rg[it] = *(const float4*)(gp[it]);
    }

    const float* x1p = smem + X1_OFF + px * STR;

    for (int ch = 0; ch < CH / CHUNK; ch++) {
#pragma unroll
        for (int it = 0; it < 5; it++)
            if (so[it] >= 0) *(float4*)(smem + so[it]) = rg[it];
        __syncthreads();

        if (ch + 1 < CH / CHUNK) {
            int cco = (ch + 1) * CHUNK;
#pragma unroll
            for (int it = 0; it < 5; it++) {
                rg[it] = make_float4(0.f, 0.f, 0.f, 0.f);
                if (so[it] >= 0 && gp[it]) rg[it] = *(const float4*)(gp[it] + cco);
            }
        }

#pragma unroll
        for (int c4 = 0; c4 < CHUNK; c4 += 4) {
            float4 qa = *(const float4*)(x1p + c4);
#pragma unroll
            for (int j = 0; j < 7; j++) {
                float4 kb = *(const float4*)(smem + nbrow[j] + c4);
                acc[j] = fmaf(qa.x, kb.x, acc[j]);
                acc[j] = fmaf(qa.y, kb.y, acc[j]);
                acc[j] = fmaf(qa.z, kb.z, acc[j]);
                acc[j] = fmaf(qa.w, kb.w, acc[j]);
            }
        }
        __syncthreads();
    }

    // ---- softmax across the 8-thread group owning pixel px ----
    float m = -1e30f;
#pragma unroll
    for (int j = 0; j < 7; j++)
        if (part + 8 * j < NK) m = fmaxf(m, acc[j]);
    m = fmaxf(m, __shfl_xor_sync(0xffffffffu, m, 1));
    m = fmaxf(m, __shfl_xor_sync(0xffffffffu, m, 2));
    m = fmaxf(m, __shfl_xor_sync(0xffffffffu, m, 4));

    float e[7];
    float s = 0.f;
#pragma unroll
    for (int j = 0; j < 7; j++) {
        int k = part + 8 * j;
        e[j] = (k < NK) ? __expf(acc[j] - m) : 0.f;
        s += e[j];
    }
    s += __shfl_xor_sync(0xffffffffu, s, 1);
    s += __shfl_xor_sync(0xffffffffu, s, 2);
    s += __shfl_xor_sync(0xffffffffu, s, 4);
    float inv = 1.f / s;
#pragma unroll
    for (int j = 0; j < 7; j++) {
        int k = part + 8 * j;
        if (k < NK) ws[px * WSTR + k] = e[j] * inv;
    }
    __syncthreads();

    // ---- Phase 2: thread = channel; two passes of 16 pixels ----
    const int c = tid;
#pragma unroll 1
    for (int hv = 0; hv < 2; hv++) {
        const int p0h = px0 + hv * 16;   // global first pixel of this pass
        const int pl0 = hv * 16;         // block-local first pixel

        float oacc[16];
#pragma unroll
        for (int i = 0; i < 16; i++) oacc[i] = 0.f;

        for (int dh = 0; dh < 7; dh++) {
            int hh = h + dh - RAD;
            if (hh < 0 || hh >= HGT) continue;          // uniform branch
            const float* vrow = g_v + (bbase + (size_t)hh * WID) * CH + c;
            const float* wsp  = ws + pl0 * WSTR + dh * 7;
#pragma unroll
            for (int wg = 0; wg < 22; wg++) {           // 16 + 6 neighborhood cols
                int gw = p0h + wg - RAD;
                float vv = (gw >= 0 && gw < WID) ? vrow[(size_t)gw * CH] : 0.f;
#pragma unroll
                for (int dw = 0; dw < 7; dw++) {
                    int pl = wg - dw;                   // compile-time per iter
                    if (pl >= 0 && pl < 16)
                        oacc[pl] = fmaf(wsp[pl * WSTR + dw], vv, oacc[pl]);
                }
            }
        }

        // transpose through smem for coalesced stores
#pragma unroll
        for (int i = 0; i < 16; i++) outS[c * STR + i] = oacc[i];
        __syncthreads();

#pragma unroll
        for (int r4 = 0; r4 < 4; r4++) {
            int idx = tid + r4 * 256;     // 0..1023 float4 units
            int cch = idx >> 2;
            int w4  = (idx & 3) << 2;
            float4 v = *(const float4*)(outS + cch * STR + w4);
            *(float4*)(out + ((size_t)(b * CH + cch) * HGT + h) * WID + p0h + w4) = v;
        }
        __syncthreads();
    }
}

// ---------------------------------------------------------------------------
extern "C" void kernel_launch(void* const* d_in, const int* in_sizes, int n_in,
                              void* d_out, int out_size)
{
    const float* x  = (const float*)d_in[0];
    const float* w1 = (const float*)d_in[1];
    const float* w2 = (const float*)d_in[2];
    const float* w3 = (const float*)d_in[3];
    float* out = (float*)d_out;
    (void)in_sizes; (void)n_in; (void)out_size;

    pre_kernel<<<272, 256>>>(x, w1, w2);

    dim3 ggrid(HW / 128, CH / 128, BATCH * 2);
    gemm_kernel<<<ggrid, 256>>>(x, w3);

    attn_kernel<<<BATCH * HGT * 2, 256>>>(out);
}

// round 11
// speedup vs baseline: 1.7428x; 1.0652x over previous
#include <cuda_runtime.h>
#include <math.h>

#define HGT   64
#define WID   64
#define CH    256
#define BATCH 4
#define HW    (HGT*WID)
#define RAD   3
#define NK    49
#define PXB   32          // pixels per attn block (half row)
#define NCB   (PXB+6)     // 38 neighborhood columns
#define X2ROWS (7*NCB)    // 266
#define CHUNK 16
#define STR   20          // smem row stride (floats) for 16-ch chunk
#define WSTR  52

// Pixel-major scratch: [B][HW][C]
__device__ float g_q[BATCH*HW*CH];   // x transposed to pixel-major (query = x)
__device__ float g_u[BATCH*HW*CH];   // u = (w1^T w2) x   (key side)
__device__ float g_v[BATCH*HW*CH];   // v = w3 x
__device__ float g_M[CH*CH];         // M[i][j] = sum_t w1[t][i] w2[t][j]

// ---------------- f32x2 packed helpers ----------------
__device__ __forceinline__ void fma2(unsigned long long& d,
                                     unsigned long long a,
                                     unsigned long long b) {
    asm("fma.rn.f32x2 %0, %1, %2, %0;" : "+l"(d) : "l"(a), "l"(b));
}
__device__ __forceinline__ unsigned long long dup2(float v) {
    unsigned long long d; unsigned r = __float_as_uint(v);
    asm("mov.b64 %0, {%1, %2};" : "=l"(d) : "r"(r), "r"(r));
    return d;
}
__device__ __forceinline__ float2 unpk(unsigned long long v) {
    unsigned lo, hi;
    asm("mov.b64 {%0, %1}, %2;" : "=r"(lo), "=r"(hi) : "l"(v));
    return make_float2(__uint_as_float(lo), __uint_as_float(hi));
}

// ---------------- cp.async helpers ----------------
__device__ __forceinline__ void cp_async16(unsigned dst, const void* src, unsigned srcsz) {
    asm volatile("cp.async.cg.shared.global [%0], [%1], 16, %2;"
                 :: "r"(dst), "l"(src), "r"(srcsz));
}
#define CP_COMMIT() asm volatile("cp.async.commit_group;")
#define CP_WAIT1()  asm volatile("cp.async.wait_group 1;")
#define CP_WAIT0()  asm volatile("cp.async.wait_group 0;")

// ---------------------------------------------------------------------------
// pre_kernel: blocks 0..1023 transpose x -> g_q (64px x 64ch jobs);
//             blocks 1024..1039 compute g_M = w1^T w2 (64x64 tiles).
// ---------------------------------------------------------------------------
__global__ __launch_bounds__(256) void pre_kernel(
    const float* __restrict__ x,
    const float* __restrict__ w1,
    const float* __restrict__ w2)
{
    __shared__ float sm[64 * 65];
    const int blk = blockIdx.x;
    const int tid = threadIdx.x;

    if (blk < 1024) {
        // ---- transpose job: (b,h) row, one 64-channel slab ----
        const int b   = blk >> 8;
        const int h   = (blk >> 2) & 63;
        const int c0  = (blk & 3) * 64;
        const float* xb = x + (size_t)b * CH * HW + (size_t)h * WID;
        float* qb = g_q + ((size_t)b * HW + (size_t)h * WID) * CH;

#pragma unroll
        for (int r = 0; r < 4; r++) {
            int u  = tid + r * 256;        // 0..1023
            int c  = u >> 4;               // 0..63
            int p4 = (u & 15) << 2;        // 0..60
            float4 v = *(const float4*)(xb + (size_t)(c0 + c) * HW + p4);
            sm[c * 65 + p4 + 0] = v.x;
            sm[c * 65 + p4 + 1] = v.y;
            sm[c * 65 + p4 + 2] = v.z;
            sm[c * 65 + p4 + 3] = v.w;
        }
        __syncthreads();
#pragma unroll
        for (int r = 0; r < 4; r++) {
            int u  = tid + r * 256;
            int p  = u >> 4;               // 0..63
            int c4 = (u & 15) << 2;        // 0..60
            float4 v = make_float4(sm[(c4 + 0) * 65 + p],
                                   sm[(c4 + 1) * 65 + p],
                                   sm[(c4 + 2) * 65 + p],
                                   sm[(c4 + 3) * 65 + p]);
            *(float4*)(qb + (size_t)p * CH + c0 + c4) = v;
        }
    } else {
        // ---- mmul: 64x64 tile of M = w1^T w2 ----
        const int t  = blk - 1024;             // 0..15
        const int i0 = (t & 3) * 64;
        const int j0 = (t >> 2) * 64;
        float* As = sm;
        float* Bs = sm + 16 * 64;

        const int ti = (tid & 15) << 2;
        const int tj = (tid >> 4) << 2;
        const int tr = tid >> 4;               // 0..15
        const int i4 = (tid & 15) << 2;

        float acc[4][4];
#pragma unroll
        for (int a = 0; a < 4; a++)
#pragma unroll
            for (int bb = 0; bb < 4; bb++) acc[a][bb] = 0.f;

        for (int k0 = 0; k0 < CH; k0 += 16) {
            *(float4*)(As + tr * 64 + i4) =
                *(const float4*)(w1 + (size_t)(k0 + tr) * CH + i0 + i4);
            *(float4*)(Bs + tr * 64 + i4) =
                *(const float4*)(w2 + (size_t)(k0 + tr) * CH + j0 + i4);
            __syncthreads();
#pragma unroll
            for (int k = 0; k < 16; k++) {
                float4 a = *(const float4*)(As + k * 64 + ti);
                float4 bv = *(const float4*)(Bs + k * 64 + tj);
                float av[4] = { a.x, a.y, a.z, a.w };
                float bw[4] = { bv.x, bv.y, bv.z, bv.w };
#pragma unroll
                for (int ii = 0; ii < 4; ii++)
#pragma unroll
                    for (int jj = 0; jj < 4; jj++)
                        acc[ii][jj] = fmaf(av[ii], bw[jj], acc[ii][jj]);
            }
            __syncthreads();
        }
#pragma unroll
        for (int ii = 0; ii < 4; ii++)
            *(float4*)(g_M + (size_t)(i0 + ti + ii) * CH + j0 + tj) =
                make_float4(acc[ii][0], acc[ii][1], acc[ii][2], acc[ii][3]);
    }
}

// ---------------------------------------------------------------------------
// GEMM: Yt[b][p][o] = sum_c W[o][c] X[b][c][p], W in {g_M -> g_u, w3 -> g_v}
// 128x128 tile, BK=8, double-buffered, FFMA2 microtile.  (unchanged)
// ---------------------------------------------------------------------------
__global__ __launch_bounds__(256) void gemm_kernel(
    const float* __restrict__ x, const float* __restrict__ w3)
{
    const int z    = blockIdx.z;        // 0..7
    const int b    = z >> 1;
    const int wsel = z & 1;
    const float* W = (wsel == 0) ? g_M : w3;
    float* Y = ((wsel == 0) ? g_u : g_v) + (size_t)b * HW * CH;
    const float* X = x + (size_t)b * CH * HW;

    const int p0 = blockIdx.x * 128;
    const int o0 = blockIdx.y * 128;

    __shared__ float As[2][8][128];
    __shared__ float Bs[2][8][128];

    const int tid = threadIdx.x;
    const int tx  = tid & 15;
    const int ty  = tid >> 4;

    const int a_cr = tid >> 5;
    const int a_p4 = (tid & 31) << 2;
    const int b_o  = tid >> 1;
    const int b_c4 = (tid & 1) << 2;

    const float* Xa = X + (size_t)a_cr * HW + p0 + a_p4;
    const float* Wb = W + (size_t)(o0 + b_o) * CH + b_c4;

    float4 ra = *(const float4*)Xa;
    float4 rb = *(const float4*)Wb;
    *(float4*)(&As[0][a_cr][a_p4]) = ra;
    Bs[0][b_c4 + 0][b_o] = rb.x;
    Bs[0][b_c4 + 1][b_o] = rb.y;
    Bs[0][b_c4 + 2][b_o] = rb.z;
    Bs[0][b_c4 + 3][b_o] = rb.w;
    __syncthreads();

    unsigned long long acc2[4][8];
#pragma unroll
    for (int i = 0; i < 4; i++)
#pragma unroll
        for (int j = 0; j < 8; j++) acc2[i][j] = 0ULL;

#pragma unroll 2
    for (int kt = 0; kt < 32; kt++) {
        const int cur = kt & 1;
        if (kt < 31) {
            ra = *(const float4*)(Xa + (size_t)(kt + 1) * 8 * HW);
            rb = *(const float4*)(Wb + (kt + 1) * 8);
        }
#pragma unroll
        for (int k = 0; k < 8; k++) {
            ulonglong2 a01 = *(const ulonglong2*)(&As[cur][k][ty * 4]);
            ulonglong2 a23 = *(const ulonglong2*)(&As[cur][k][64 + ty * 4]);
            float4 bv0 = *(const float4*)(&Bs[cur][k][tx * 4]);
            float4 bv1 = *(const float4*)(&Bs[cur][k][64 + tx * 4]);
            unsigned long long av[4] = { a01.x, a01.y, a23.x, a23.y };
            unsigned long long bd[8];
            bd[0] = dup2(bv0.x); bd[1] = dup2(bv0.y);
            bd[2] = dup2(bv0.z); bd[3] = dup2(bv0.w);
            bd[4] = dup2(bv1.x); bd[5] = dup2(bv1.y);
            bd[6] = dup2(bv1.z); bd[7] = dup2(bv1.w);
#pragma unroll
            for (int i2 = 0; i2 < 4; i2++)
#pragma unroll
                for (int j = 0; j < 8; j++)
                    fma2(acc2[i2][j], av[i2], bd[j]);
        }
        if (kt < 31) {
            const int nxt = cur ^ 1;
            *(float4*)(&As[nxt][a_cr][a_p4]) = ra;
            Bs[nxt][b_c4 + 0][b_o] = rb.x;
            Bs[nxt][b_c4 + 1][b_o] = rb.y;
            Bs[nxt][b_c4 + 2][b_o] = rb.z;
            Bs[nxt][b_c4 + 3][b_o] = rb.w;
            __syncthreads();
        }
    }

#pragma unroll
    for (int i2 = 0; i2 < 4; i2++) {
        const int prow = p0 + ((i2 < 2) ? (ty * 4 + 2 * i2)
                                        : (64 + ty * 4 + 2 * (i2 - 2)));
        float lo[8], hi[8];
#pragma unroll
        for (int j = 0; j < 8; j++) {
            float2 t = unpk(acc2[i2][j]);
            lo[j] = t.x; hi[j] = t.y;
        }
        float* yl = Y + (size_t)prow * CH + o0;
        *(float4*)(yl + tx * 4)      = make_float4(lo[0], lo[1], lo[2], lo[3]);
        *(float4*)(yl + 64 + tx * 4) = make_float4(lo[4], lo[5], lo[6], lo[7]);
        float* yh = yl + CH;
        *(float4*)(yh + tx * 4)      = make_float4(hi[0], hi[1], hi[2], hi[3]);
        *(float4*)(yh + 64 + tx * 4) = make_float4(hi[4], hi[5], hi[6], hi[7]);
    }
}

// ---------------------------------------------------------------------------
// Attention: block = (b, h, half-row of 32 px). 256 threads.
// Staging via cp.async 2-stage pipeline (chunk ch+2 in flight while ch computes).
// Compute / softmax / phase 2 identical to the proven R5 kernel.
// Dynamic smem (floats): ws[1664] | buf0[5960] | buf1[5960] = 13584 (54.3KB)
//   buffer layout: x1[32*20]=640 then x2[266*20]=5320.
//   outS (phase 2) aliases buf0.
// ---------------------------------------------------------------------------
#define WS_OFF   0
#define BUF0     1664
#define BUFSZ    (PXB*STR + X2ROWS*STR)     // 5960
#define X2_REL   (PXB*STR)                  // 640
#define OUTS_OFF BUF0
#define SMEM_FLOATS (1664 + 2*BUFSZ)        // 13584
#define NUNITS   (PXB*4 + X2ROWS*4)         // 1192 float4 staging units / chunk

__global__ __launch_bounds__(256) void attn_kernel(float* __restrict__ out)
{
    extern __shared__ float smem[];
    float* ws   = smem + WS_OFF;
    float* outS = smem + OUTS_OFF;

    const int blk  = blockIdx.x;          // b*128 + h*2 + half
    const int b    = blk >> 7;
    const int h    = (blk >> 1) & 63;
    const int half = blk & 1;
    const int px0  = half * PXB;
    const int tid  = threadIdx.x;

    const int px   = tid >> 3;            // 0..31
    const int part = tid & 7;             // 0..7

    const size_t bbase = (size_t)b * HW;
    const unsigned smem_u32 =
        (unsigned)__cvta_generic_to_shared(smem);

    // ---- staging plan: 5 float4 units per thread, computed once ----
    const float* gp[5];
    int so[5];                            // within-buffer float offset, -1 = none
#pragma unroll
    for (int it = 0; it < 5; it++) {
        int unit = tid + it * 256;
        gp[it] = 0; so[it] = -1;
        if (unit < PXB * 4) {
            int p  = unit >> 2;
            int c4 = (unit & 3) << 2;
            gp[it] = g_q + (bbase + (size_t)h * WID + px0 + p) * CH + c4;
            so[it] = p * STR + c4;
        } else if (unit < NUNITS) {
            int u   = unit - PXB * 4;
            int row = u >> 2;
            int c4  = (u & 3) << 2;
            int dh  = row / NCB;
            int col = row - dh * NCB;
            int hh  = h + dh - RAD;
            int gw  = px0 + col - RAD;
            so[it] = X2_REL + row * STR + c4;
            if (hh >= 0 && hh < HGT && gw >= 0 && gw < WID)
                gp[it] = g_u + (bbase + (size_t)hh * WID + gw) * CH + c4;
        }
    }

    // ---- per-thread logit rows (buffer-relative offsets) ----
    float acc[7];
    int   nbrow[7];
#pragma unroll
    for (int j = 0; j < 7; j++) {
        acc[j] = 0.f;
        int k  = part + 8 * j;
        int kk = (k < NK) ? k : 0;
        int dh = kk / 7, dw = kk - dh * 7;
        nbrow[j] = X2_REL + (dh * NCB + px + dw) * STR;
    }

    // ---- issue chunks 0 and 1 ----
#pragma unroll
    for (int pc = 0; pc < 2; pc++) {
        const unsigned base = smem_u32 + (BUF0 + pc * BUFSZ) * 4u;
#pragma unroll
        for (int it = 0; it < 5; it++) {
            if (so[it] >= 0) {
                const float* src = gp[it] ? (gp[it] + pc * CHUNK) : (const float*)g_q;
                cp_async16(base + so[it] * 4u, src, gp[it] ? 16u : 0u);
            }
        }
        CP_COMMIT();
    }

    for (int ch = 0; ch < CH / CHUNK; ch++) {
        if (ch == CH / CHUNK - 1) { CP_WAIT0(); } else { CP_WAIT1(); }
        __syncthreads();

        const float* bp  = smem + BUF0 + (ch & 1) * BUFSZ;
        const float* x1p = bp + px * STR;
#pragma unroll
        for (int c4 = 0; c4 < CHUNK; c4 += 4) {
            float4 qa = *(const float4*)(x1p + c4);
#pragma unroll
            for (int j = 0; j < 7; j++) {
                float4 kb = *(const float4*)(bp + nbrow[j] + c4);
                acc[j] = fmaf(qa.x, kb.x, acc[j]);
                acc[j] = fmaf(qa.y, kb.y, acc[j]);
                acc[j] = fmaf(qa.z, kb.z, acc[j]);
                acc[j] = fmaf(qa.w, kb.w, acc[j]);
            }
        }
        __syncthreads();

        if (ch + 2 < CH / CHUNK) {
            const int cco = (ch + 2) * CHUNK;
            const unsigned base = smem_u32 + (BUF0 + (ch & 1) * BUFSZ) * 4u;
#pragma unroll
            for (int it = 0; it < 5; it++) {
                if (so[it] >= 0) {
                    const float* src = gp[it] ? (gp[it] + cco) : (const float*)g_q;
                    cp_async16(base + so[it] * 4u, src, gp[it] ? 16u : 0u);
                }
            }
            CP_COMMIT();
        }
    }

    // ---- softmax across the 8-thread group owning pixel px ----
    float m = -1e30f;
#pragma unroll
    for (int j = 0; j < 7; j++)
        if (part + 8 * j < NK) m = fmaxf(m, acc[j]);
    m = fmaxf(m, __shfl_xor_sync(0xffffffffu, m, 1));
    m = fmaxf(m, __shfl_xor_sync(0xffffffffu, m, 2));
    m = fmaxf(m, __shfl_xor_sync(0xffffffffu, m, 4));

    float e[7];
    float s = 0.f;
#pragma unroll
    for (int j = 0; j < 7; j++) {
        int k = part + 8 * j;
        e[j] = (k < NK) ? __expf(acc[j] - m) : 0.f;
        s += e[j];
    }
    s += __shfl_xor_sync(0xffffffffu, s, 1);
    s += __shfl_xor_sync(0xffffffffu, s, 2);
    s += __shfl_xor_sync(0xffffffffu, s, 4);
    float inv = 1.f / s;
#pragma unroll
    for (int j = 0; j < 7; j++) {
        int k = part + 8 * j;
        if (k < NK) ws[px * WSTR + k] = e[j] * inv;
    }
    __syncthreads();

    // ---- Phase 2: thread = channel; two passes of 16 pixels ----
    const int c = tid;
#pragma unroll 1
    for (int hv = 0; hv < 2; hv++) {
        const int p0h = px0 + hv * 16;   // global first pixel of this pass
        const int pl0 = hv * 16;         // block-local first pixel

        float oacc[16];
#pragma unroll
        for (int i = 0; i < 16; i++) oacc[i] = 0.f;

        for (int dh = 0; dh < 7; dh++) {
            int hh = h + dh - RAD;
            if (hh < 0 || hh >= HGT) continue;          // uniform branch
            const float* vrow = g_v + (bbase + (size_t)hh * WID) * CH + c;
            const float* wsp  = ws + pl0 * WSTR + dh * 7;
#pragma unroll
            for (int wg = 0; wg < 22; wg++) {           // 16 + 6 neighborhood cols
                int gw = p0h + wg - RAD;
                float vv = (gw >= 0 && gw < WID) ? vrow[(size_t)gw * CH] : 0.f;
#pragma unroll
                for (int dw = 0; dw < 7; dw++) {
                    int pl = wg - dw;                   // compile-time per iter
                    if (pl >= 0 && pl < 16)
                        oacc[pl] = fmaf(wsp[pl * WSTR + dw], vv, oacc[pl]);
                }
            }
        }

        // transpose through smem for coalesced stores
#pragma unroll
        for (int i = 0; i < 16; i++) outS[c * STR + i] = oacc[i];
        __syncthreads();

#pragma unroll
        for (int r4 = 0; r4 < 4; r4++) {
            int idx = tid + r4 * 256;     // 0..1023 float4 units
            int cch = idx >> 2;
            int w4  = (idx & 3) << 2;
            float4 v = *(const float4*)(outS + cch * STR + w4);
            *(float4*)(out + ((size_t)(b * CH + cch) * HGT + h) * WID + p0h + w4) = v;
        }
        __syncthreads();
    }
}

// ---------------------------------------------------------------------------
extern "C" void kernel_launch(void* const* d_in, const int* in_sizes, int n_in,
                              void* d_out, int out_size)
{
    const float* x  = (const float*)d_in[0];
    const float* w1 = (const float*)d_in[1];
    const float* w2 = (const float*)d_in[2];
    const float* w3 = (const float*)d_in[3];
    float* out = (float*)d_out;
    (void)in_sizes; (void)n_in; (void)out_size;

    cudaFuncSetAttribute(attn_kernel,
                         cudaFuncAttributeMaxDynamicSharedMemorySize,
                         SMEM_FLOATS * (int)sizeof(float));

    pre_kernel<<<1040, 256>>>(x, w1, w2);

    dim3 ggrid(HW / 128, CH / 128, BATCH * 2);
    gemm_kernel<<<ggrid, 256>>>(x, w3);

    attn_kernel<<<BATCH * HGT * 2, 256, SMEM_FLOATS * sizeof(float)>>>(out);
}

// round 16
// speedup vs baseline: 1.8115x; 1.0394x over previous
#include <cuda_runtime.h>
#include <math.h>

#define HGT   64
#define WID   64
#define CH    256
#define BATCH 4
#define HW    (HGT*WID)
#define RAD   3
#define NK    49
#define PXB   32          // pixels per attn block (half row)
#define NCB   (PXB+6)     // 38 neighborhood columns
#define X2ROWS (7*NCB)    // 266
#define CHUNK 16
#define STR   20          // smem row stride (floats) for 16-ch chunk
#define WSTR  52

// Pixel-major scratch: [B][HW][C]
__device__ float g_q[BATCH*HW*CH];   // x transposed to pixel-major (query = x)
__device__ float g_u[BATCH*HW*CH];   // u = (w1^T w2) x   (key side)
__device__ float g_v[BATCH*HW*CH];   // v = w3 x
__device__ float g_M[CH*CH];         // M[i][j] = sum_t w1[t][i] w2[t][j]

// ---------------- f32x2 packed helpers ----------------
__device__ __forceinline__ void fma2(unsigned long long& d,
                                     unsigned long long a,
                                     unsigned long long b) {
    asm("fma.rn.f32x2 %0, %1, %2, %0;" : "+l"(d) : "l"(a), "l"(b));
}
__device__ __forceinline__ unsigned long long dup2(float v) {
    unsigned long long d; unsigned r = __float_as_uint(v);
    asm("mov.b64 %0, {%1, %2};" : "=l"(d) : "r"(r), "r"(r));
    return d;
}
__device__ __forceinline__ float2 unpk(unsigned long long v) {
    unsigned lo, hi;
    asm("mov.b64 {%0, %1}, %2;" : "=r"(lo), "=r"(hi) : "l"(v));
    return make_float2(__uint_as_float(lo), __uint_as_float(hi));
}

// ---------------- cp.async helpers ----------------
__device__ __forceinline__ void cp_async16(unsigned dst, const void* src, unsigned srcsz) {
    asm volatile("cp.async.cg.shared.global [%0], [%1], 16, %2;"
                 :: "r"(dst), "l"(src), "r"(srcsz));
}
#define CP_COMMIT() asm volatile("cp.async.commit_group;")
#define CP_WAIT1()  asm volatile("cp.async.wait_group 1;")
#define CP_WAIT0()  asm volatile("cp.async.wait_group 0;")

// ---------------------------------------------------------------------------
// mmul_kernel: g_M = w1^T w2 (16 blocks, 64x64 tiles, register-prefetch DB).
// ---------------------------------------------------------------------------
__global__ __launch_bounds__(256) void mmul_kernel(
    const float* __restrict__ w1, const float* __restrict__ w2)
{
    __shared__ float As[16 * 64];
    __shared__ float Bs[16 * 64];

    const int t  = blockIdx.x;             // 0..15
    const int i0 = (t & 3) * 64;
    const int j0 = (t >> 2) * 64;
    const int tid = threadIdx.x;

    const int ti = (tid & 15) << 2;
    const int tj = (tid >> 4) << 2;
    const int tr = tid >> 4;               // 0..15
    const int i4 = (tid & 15) << 2;

    float acc[4][4];
#pragma unroll
    for (int a = 0; a < 4; a++)
#pragma unroll
        for (int bb = 0; bb < 4; bb++) acc[a][bb] = 0.f;

    float4 na = *(const float4*)(w1 + (size_t)tr * CH + i0 + i4);
    float4 nb = *(const float4*)(w2 + (size_t)tr * CH + j0 + i4);

    for (int k0 = 0; k0 < CH; k0 += 16) {
        *(float4*)(As + tr * 64 + i4) = na;
        *(float4*)(Bs + tr * 64 + i4) = nb;
        __syncthreads();
        if (k0 + 16 < CH) {
            na = *(const float4*)(w1 + (size_t)(k0 + 16 + tr) * CH + i0 + i4);
            nb = *(const float4*)(w2 + (size_t)(k0 + 16 + tr) * CH + j0 + i4);
        }
#pragma unroll
        for (int k = 0; k < 16; k++) {
            float4 a  = *(const float4*)(As + k * 64 + ti);
            float4 bv = *(const float4*)(Bs + k * 64 + tj);
            float av[4] = { a.x, a.y, a.z, a.w };
            float bw[4] = { bv.x, bv.y, bv.z, bv.w };
#pragma unroll
            for (int ii = 0; ii < 4; ii++)
#pragma unroll
                for (int jj = 0; jj < 4; jj++)
                    acc[ii][jj] = fmaf(av[ii], bw[jj], acc[ii][jj]);
        }
        __syncthreads();
    }
#pragma unroll
    for (int ii = 0; ii < 4; ii++)
        *(float4*)(g_M + (size_t)(i0 + ti + ii) * CH + j0 + tj) =
            make_float4(acc[ii][0], acc[ii][1], acc[ii][2], acc[ii][3]);
}

// ---------------------------------------------------------------------------
// GEMM: Yt[b][p][o] = sum_c W[o][c] X[b][c][p], W in {g_M -> g_u, w3 -> g_v}
// 128x128 tile, BK=8, double-buffered, FFMA2 microtile.
// Side-output: blocks with o0==0 write the As tiles transposed to g_q
// (x pixel-major). Stage parity split between wsel 0/1 so each covers half.
// ---------------------------------------------------------------------------
__global__ __launch_bounds__(256) void gemm_kernel(
    const float* __restrict__ x, const float* __restrict__ w3)
{
    const int z    = blockIdx.z;        // 0..7
    const int b    = z >> 1;
    const int wsel = z & 1;
    const float* W = (wsel == 0) ? g_M : w3;
    float* Y = ((wsel == 0) ? g_u : g_v) + (size_t)b * HW * CH;
    const float* X = x + (size_t)b * CH * HW;
    float* Q = g_q + (size_t)b * HW * CH;

    const int p0 = blockIdx.x * 128;
    const int o0 = blockIdx.y * 128;
    const bool do_tr = (o0 == 0);

    __shared__ float As[2][8][128];
    __shared__ float Bs[2][8][128];

    const int tid = threadIdx.x;
    const int tx  = tid & 15;
    const int ty  = tid >> 4;

    const int a_cr = tid >> 5;
    const int a_p4 = (tid & 31) << 2;
    const int b_o  = tid >> 1;
    const int b_c4 = (tid & 1) << 2;

    // transpose thread map: p = tid>>1 (0..127), c4 = (tid&1)*4
    const int t_p  = tid >> 1;
    const int t_c4 = (tid & 1) << 2;

    const float* Xa = X + (size_t)a_cr * HW + p0 + a_p4;
    const float* Wb = W + (size_t)(o0 + b_o) * CH + b_c4;

    float4 ra = *(const float4*)Xa;
    float4 rb = *(const float4*)Wb;
    *(float4*)(&As[0][a_cr][a_p4]) = ra;
    Bs[0][b_c4 + 0][b_o] = rb.x;
    Bs[0][b_c4 + 1][b_o] = rb.y;
    Bs[0][b_c4 + 2][b_o] = rb.z;
    Bs[0][b_c4 + 3][b_o] = rb.w;
    __syncthreads();

    unsigned long long acc2[4][8];
#pragma unroll
    for (int i = 0; i < 4; i++)
#pragma unroll
        for (int j = 0; j < 8; j++) acc2[i][j] = 0ULL;

#pragma unroll 2
    for (int kt = 0; kt < 32; kt++) {
        const int cur = kt & 1;
        if (kt < 31) {
            ra = *(const float4*)(Xa + (size_t)(kt + 1) * 8 * HW);
            rb = *(const float4*)(Wb + (kt + 1) * 8);
        }
#pragma unroll
        for (int k = 0; k < 8; k++) {
            ulonglong2 a01 = *(const ulonglong2*)(&As[cur][k][ty * 4]);
            ulonglong2 a23 = *(const ulonglong2*)(&As[cur][k][64 + ty * 4]);
            float4 bv0 = *(const float4*)(&Bs[cur][k][tx * 4]);
            float4 bv1 = *(const float4*)(&Bs[cur][k][64 + tx * 4]);
            unsigned long long av[4] = { a01.x, a01.y, a23.x, a23.y };
            unsigned long long bd[8];
            bd[0] = dup2(bv0.x); bd[1] = dup2(bv0.y);
            bd[2] = dup2(bv0.z); bd[3] = dup2(bv0.w);
            bd[4] = dup2(bv1.x); bd[5] = dup2(bv1.y);
            bd[6] = dup2(bv1.z); bd[7] = dup2(bv1.w);
#pragma unroll
            for (int i2 = 0; i2 < 4; i2++)
#pragma unroll
                for (int j = 0; j < 8; j++)
                    fma2(acc2[i2][j], av[i2], bd[j]);
        }

        // transpose side-output: x[kt*8 + c][p0+p] -> g_q[(p0+p)*CH + kt*8 + c]
        if (do_tr && ((kt & 1) == wsel)) {
            float4 v = make_float4(As[cur][t_c4 + 0][t_p],
                                   As[cur][t_c4 + 1][t_p],
                                   As[cur][t_c4 + 2][t_p],
                                   As[cur][t_c4 + 3][t_p]);
            *(float4*)(Q + (size_t)(p0 + t_p) * CH + kt * 8 + t_c4) = v;
        }

        if (kt < 31) {
            const int nxt = cur ^ 1;
            *(float4*)(&As[nxt][a_cr][a_p4]) = ra;
            Bs[nxt][b_c4 + 0][b_o] = rb.x;
            Bs[nxt][b_c4 + 1][b_o] = rb.y;
            Bs[nxt][b_c4 + 2][b_o] = rb.z;
            Bs[nxt][b_c4 + 3][b_o] = rb.w;
            __syncthreads();
        }
    }

#pragma unroll
    for (int i2 = 0; i2 < 4; i2++) {
        const int prow = p0 + ((i2 < 2) ? (ty * 4 + 2 * i2)
                                        : (64 + ty * 4 + 2 * (i2 - 2)));
        float lo[8], hi[8];
#pragma unroll
        for (int j = 0; j < 8; j++) {
            float2 t = unpk(acc2[i2][j]);
            lo[j] = t.x; hi[j] = t.y;
        }
        float* yl = Y + (size_t)prow * CH + o0;
        *(float4*)(yl + tx * 4)      = make_float4(lo[0], lo[1], lo[2], lo[3]);
        *(float4*)(yl + 64 + tx * 4) = make_float4(lo[4], lo[5], lo[6], lo[7]);
        float* yh = yl + CH;
        *(float4*)(yh + tx * 4)      = make_float4(hi[0], hi[1], hi[2], hi[3]);
        *(float4*)(yh + 64 + tx * 4) = make_float4(hi[4], hi[5], hi[6], hi[7]);
    }
}

// ---------------------------------------------------------------------------
// Attention: block = (b, h, half-row of 32 px). 256 threads.  (R11 verbatim)
// cp.async 2-stage pipeline; compute/softmax/phase2 = proven R5 code.
// ---------------------------------------------------------------------------
#define WS_OFF   0
#define BUF0     1664
#define BUFSZ    (PXB*STR + X2ROWS*STR)     // 5960
#define X2_REL   (PXB*STR)                  // 640
#define OUTS_OFF BUF0
#define SMEM_FLOATS (1664 + 2*BUFSZ)        // 13584
#define NUNITS   (PXB*4 + X2ROWS*4)         // 1192 float4 staging units / chunk

__global__ __launch_bounds__(256) void attn_kernel(float* __restrict__ out)
{
    extern __shared__ float smem[];
    float* ws   = smem + WS_OFF;
    float* outS = smem + OUTS_OFF;

    const int blk  = blockIdx.x;          // b*128 + h*2 + half
    const int b    = blk >> 7;
    const int h    = (blk >> 1) & 63;
    const int half = blk & 1;
    const int px0  = half * PXB;
    const int tid  = threadIdx.x;

    const int px   = tid >> 3;            // 0..31
    const int part = tid & 7;             // 0..7

    const size_t bbase = (size_t)b * HW;
    const unsigned smem_u32 =
        (unsigned)__cvta_generic_to_shared(smem);

    // ---- staging plan: 5 float4 units per thread, computed once ----
    const float* gp[5];
    int so[5];                            // within-buffer float offset, -1 = none
#pragma unroll
    for (int it = 0; it < 5; it++) {
        int unit = tid + it * 256;
        gp[it] = 0; so[it] = -1;
        if (unit < PXB * 4) {
            int p  = unit >> 2;
            int c4 = (unit & 3) << 2;
            gp[it] = g_q + (bbase + (size_t)h * WID + px0 + p) * CH + c4;
            so[it] = p * STR + c4;
        } else if (unit < NUNITS) {
            int u   = unit - PXB * 4;
            int row = u >> 2;
            int c4  = (u & 3) << 2;
            int dh  = row / NCB;
            int col = row - dh * NCB;
            int hh  = h + dh - RAD;
            int gw  = px0 + col - RAD;
            so[it] = X2_REL + row * STR + c4;
            if (hh >= 0 && hh < HGT && gw >= 0 && gw < WID)
                gp[it] = g_u + (bbase + (size_t)hh * WID + gw) * CH + c4;
        }
    }

    // ---- per-thread logit rows (buffer-relative offsets) ----
    float acc[7];
    int   nbrow[7];
#pragma unroll
    for (int j = 0; j < 7; j++) {
        acc[j] = 0.f;
        int k  = part + 8 * j;
        int kk = (k < NK) ? k : 0;
        int dh = kk / 7, dw = kk - dh * 7;
        nbrow[j] = X2_REL + (dh * NCB + px + dw) * STR;
    }

    // ---- issue chunks 0 and 1 ----
#pragma unroll
    for (int pc = 0; pc < 2; pc++) {
        const unsigned base = smem_u32 + (BUF0 + pc * BUFSZ) * 4u;
#pragma unroll
        for (int it = 0; it < 5; it++) {
            if (so[it] >= 0) {
                const float* src = gp[it] ? (gp[it] + pc * CHUNK) : (const float*)g_q;
                cp_async16(base + so[it] * 4u, src, gp[it] ? 16u : 0u);
            }
        }
        CP_COMMIT();
    }

    for (int ch = 0; ch < CH / CHUNK; ch++) {
        if (ch == CH / CHUNK - 1) { CP_WAIT0(); } else { CP_WAIT1(); }
        __syncthreads();

        const float* bp  = smem + BUF0 + (ch & 1) * BUFSZ;
        const float* x1p = bp + px * STR;
#pragma unroll
        for (int c4 = 0; c4 < CHUNK; c4 += 4) {
            float4 qa = *(const float4*)(x1p + c4);
#pragma unroll
            for (int j = 0; j < 7; j++) {
                float4 kb = *(const float4*)(bp + nbrow[j] + c4);
                acc[j] = fmaf(qa.x, kb.x, acc[j]);
                acc[j] = fmaf(qa.y, kb.y, acc[j]);
                acc[j] = fmaf(qa.z, kb.z, acc[j]);
                acc[j] = fmaf(qa.w, kb.w, acc[j]);
            }
        }
        __syncthreads();

        if (ch + 2 < CH / CHUNK) {
            const int cco = (ch + 2) * CHUNK;
            const unsigned base = smem_u32 + (BUF0 + (ch & 1) * BUFSZ) * 4u;
#pragma unroll
            for (int it = 0; it < 5; it++) {
                if (so[it] >= 0) {
                    const float* src = gp[it] ? (gp[it] + cco) : (const float*)g_q;
                    cp_async16(base + so[it] * 4u, src, gp[it] ? 16u : 0u);
                }
            }
            CP_COMMIT();
        }
    }

    // ---- softmax across the 8-thread group owning pixel px ----
    float m = -1e30f;
#pragma unroll
    for (int j = 0; j < 7; j++)
        if (part + 8 * j < NK) m = fmaxf(m, acc[j]);
    m = fmaxf(m, __shfl_xor_sync(0xffffffffu, m, 1));
    m = fmaxf(m, __shfl_xor_sync(0xffffffffu, m, 2));
    m = fmaxf(m, __shfl_xor_sync(0xffffffffu, m, 4));

    float e[7];
    float s = 0.f;
#pragma unroll
    for (int j = 0; j < 7; j++) {
        int k = part + 8 * j;
        e[j] = (k < NK) ? __expf(acc[j] - m) : 0.f;
        s += e[j];
    }
    s += __shfl_xor_sync(0xffffffffu, s, 1);
    s += __shfl_xor_sync(0xffffffffu, s, 2);
    s += __shfl_xor_sync(0xffffffffu, s, 4);
    float inv = 1.f / s;
#pragma unroll
    for (int j = 0; j < 7; j++) {
        int k = part + 8 * j;
        if (k < NK) ws[px * WSTR + k] = e[j] * inv;
    }
    __syncthreads();

    // ---- Phase 2: thread = channel; two passes of 16 pixels ----
    const int c = tid;
#pragma unroll 1
    for (int hv = 0; hv < 2; hv++) {
        const int p0h = px0 + hv * 16;   // global first pixel of this pass
        const int pl0 = hv * 16;         // block-local first pixel

        float oacc[16];
#pragma unroll
        for (int i = 0; i < 16; i++) oacc[i] = 0.f;

        for (int dh = 0; dh < 7; dh++) {
            int hh = h + dh - RAD;
            if (hh < 0 || hh >= HGT) continue;          // uniform branch
            const float* vrow = g_v + (bbase + (size_t)hh * WID) * CH + c;
            const float* wsp  = ws + pl0 * WSTR + dh * 7;
#pragma unroll
            for (int wg = 0; wg < 22; wg++) {           // 16 + 6 neighborhood cols
                int gw = p0h + wg - RAD;
                float vv = (gw >= 0 && gw < WID) ? vrow[(size_t)gw * CH] : 0.f;
#pragma unroll
                for (int dw = 0; dw < 7; dw++) {
                    int pl = wg - dw;                   // compile-time per iter
                    if (pl >= 0 && pl < 16)
                        oacc[pl] = fmaf(wsp[pl * WSTR + dw], vv, oacc[pl]);
                }
            }
        }

        // transpose through smem for coalesced stores
#pragma unroll
        for (int i = 0; i < 16; i++) outS[c * STR + i] = oacc[i];
        __syncthreads();

#pragma unroll
        for (int r4 = 0; r4 < 4; r4++) {
            int idx = tid + r4 * 256;     // 0..1023 float4 units
            int cch = idx >> 2;
            int w4  = (idx & 3) << 2;
            float4 v = *(const float4*)(outS + cch * STR + w4);
            *(float4*)(out + ((size_t)(b * CH + cch) * HGT + h) * WID + p0h + w4) = v;
        }
        __syncthreads();
    }
}

// ---------------------------------------------------------------------------
extern "C" void kernel_launch(void* const* d_in, const int* in_sizes, int n_in,
                              void* d_out, int out_size)
{
    const float* x  = (const float*)d_in[0];
    const float* w1 = (const float*)d_in[1];
    const float* w2 = (const float*)d_in[2];
    const float* w3 = (const float*)d_in[3];
    float* out = (float*)d_out;
    (void)in_sizes; (void)n_in; (void)out_size;

    cudaFuncSetAttribute(attn_kernel,
                         cudaFuncAttributeMaxDynamicSharedMemorySize,
                         SMEM_FLOATS * (int)sizeof(float));

    mmul_kernel<<<16, 256>>>(w1, w2);

    dim3 ggrid(HW / 128, CH / 128, BATCH * 2);
    gemm_kernel<<<ggrid, 256>>>(x, w3);

    attn_kernel<<<BATCH * HGT * 2, 256, SMEM_FLOATS * sizeof(float)>>>(out);
}

// round 17
// speedup vs baseline: 1.8671x; 1.0307x over previous
#include <cuda_runtime.h>
#include <math.h>

#define HGT   64
#define WID   64
#define CH    256
#define BATCH 4
#define HW    (HGT*WID)
#define RAD   3
#define NK    49
#define PXB   32          // pixels per attn block (half row)
#define NCB   (PXB+6)     // 38 neighborhood columns
#define X2ROWS (7*NCB)    // 266
#define CHUNK 16
#define STR   20          // smem row stride (floats) for 16-ch chunk
#define WSTR  52

// Pixel-major scratch: [B][HW][C]
__device__ float g_q[BATCH*HW*CH];   // x transposed to pixel-major (query = x)
__device__ float g_u[BATCH*HW*CH];   // u = (w1^T w2) x   (key side)
__device__ float g_v[BATCH*HW*CH];   // v = w3 x
__device__ float g_M[CH*CH];         // M[i][j] = sum_t w1[t][i] w2[t][j]

// ---------------- f32x2 packed helpers ----------------
__device__ __forceinline__ void fma2(unsigned long long& d,
                                     unsigned long long a,
                                     unsigned long long b) {
    asm("fma.rn.f32x2 %0, %1, %2, %0;" : "+l"(d) : "l"(a), "l"(b));
}
__device__ __forceinline__ unsigned long long dup2(float v) {
    unsigned long long d; unsigned r = __float_as_uint(v);
    asm("mov.b64 %0, {%1, %2};" : "=l"(d) : "r"(r), "r"(r));
    return d;
}
__device__ __forceinline__ float2 unpk(unsigned long long v) {
    unsigned lo, hi;
    asm("mov.b64 {%0, %1}, %2;" : "=r"(lo), "=r"(hi) : "l"(v));
    return make_float2(__uint_as_float(lo), __uint_as_float(hi));
}

// ---------------- cp.async helpers ----------------
__device__ __forceinline__ void cp_async16(unsigned dst, const void* src, unsigned srcsz) {
    asm volatile("cp.async.cg.shared.global [%0], [%1], 16, %2;"
                 :: "r"(dst), "l"(src), "r"(srcsz));
}
#define CP_COMMIT() asm volatile("cp.async.commit_group;")
#define CP_WAIT1()  asm volatile("cp.async.wait_group 1;")
#define CP_WAIT0()  asm volatile("cp.async.wait_group 0;")

// ---------------------------------------------------------------------------
// Kernel A: blocks 0..255 = v-GEMM (v = w3 x, all batches) + x-transpose
//           side-output (o0==0 blocks); blocks 256..271 = mmul (M = w1^T w2).
// The 16 mmul blocks hide entirely under the 256-block v-GEMM wave.
// ---------------------------------------------------------------------------
__global__ __launch_bounds__(256) void gemm_v_mmul_kernel(
    const float* __restrict__ x,
    const float* __restrict__ w1,
    const float* __restrict__ w2,
    const float* __restrict__ w3)
{
    __shared__ float As[2][8][128];
    __shared__ float Bs[2][8][128];

    const int blk = blockIdx.x;
    const int tid = threadIdx.x;

    if (blk >= 256) {
        // ---- mmul: 64x64 tile of M = w1^T w2, register-prefetch DB ----
        float* As1 = &As[0][0][0];        // 1024 floats
        float* Bs1 = &Bs[0][0][0];

        const int t  = blk - 256;          // 0..15
        const int i0 = (t & 3) * 64;
        const int j0 = (t >> 2) * 64;

        const int ti = (tid & 15) << 2;
        const int tj = (tid >> 4) << 2;
        const int tr = tid >> 4;           // 0..15
        const int i4 = (tid & 15) << 2;

        float acc[4][4];
#pragma unroll
        for (int a = 0; a < 4; a++)
#pragma unroll
            for (int bb = 0; bb < 4; bb++) acc[a][bb] = 0.f;

        float4 na = *(const float4*)(w1 + (size_t)tr * CH + i0 + i4);
        float4 nb = *(const float4*)(w2 + (size_t)tr * CH + j0 + i4);

        for (int k0 = 0; k0 < CH; k0 += 16) {
            *(float4*)(As1 + tr * 64 + i4) = na;
            *(float4*)(Bs1 + tr * 64 + i4) = nb;
            __syncthreads();
            if (k0 + 16 < CH) {
                na = *(const float4*)(w1 + (size_t)(k0 + 16 + tr) * CH + i0 + i4);
                nb = *(const float4*)(w2 + (size_t)(k0 + 16 + tr) * CH + j0 + i4);
            }
#pragma unroll
            for (int k = 0; k < 16; k++) {
                float4 a  = *(const float4*)(As1 + k * 64 + ti);
                float4 bv = *(const float4*)(Bs1 + k * 64 + tj);
                float av[4] = { a.x, a.y, a.z, a.w };
                float bw[4] = { bv.x, bv.y, bv.z, bv.w };
#pragma unroll
                for (int ii = 0; ii < 4; ii++)
#pragma unroll
                    for (int jj = 0; jj < 4; jj++)
                        acc[ii][jj] = fmaf(av[ii], bw[jj], acc[ii][jj]);
            }
            __syncthreads();
        }
#pragma unroll
        for (int ii = 0; ii < 4; ii++)
            *(float4*)(g_M + (size_t)(i0 + ti + ii) * CH + j0 + tj) =
                make_float4(acc[ii][0], acc[ii][1], acc[ii][2], acc[ii][3]);
        return;
    }

    // ---- v-GEMM block ----
    const int b  = blk >> 6;
    const int r  = blk & 63;
    const int p0 = (r & 31) * 128;
    const int o0 = (r >> 5) * 128;
    const bool do_tr = (o0 == 0);

    const float* X = x + (size_t)b * CH * HW;
    float* Y = g_v + (size_t)b * HW * CH;
    float* Q = g_q + (size_t)b * HW * CH;

    const int tx  = tid & 15;
    const int ty  = tid >> 4;

    const int a_cr = tid >> 5;
    const int a_p4 = (tid & 31) << 2;
    const int b_o  = tid >> 1;
    const int b_c4 = (tid & 1) << 2;

    const int t_p  = tid >> 1;
    const int t_c4 = (tid & 1) << 2;

    const float* Xa = X + (size_t)a_cr * HW + p0 + a_p4;
    const float* Wb = w3 + (size_t)(o0 + b_o) * CH + b_c4;

    float4 ra = *(const float4*)Xa;
    float4 rb = *(const float4*)Wb;
    *(float4*)(&As[0][a_cr][a_p4]) = ra;
    Bs[0][b_c4 + 0][b_o] = rb.x;
    Bs[0][b_c4 + 1][b_o] = rb.y;
    Bs[0][b_c4 + 2][b_o] = rb.z;
    Bs[0][b_c4 + 3][b_o] = rb.w;
    __syncthreads();

    unsigned long long acc2[4][8];
#pragma unroll
    for (int i = 0; i < 4; i++)
#pragma unroll
        for (int j = 0; j < 8; j++) acc2[i][j] = 0ULL;

#pragma unroll 2
    for (int kt = 0; kt < 32; kt++) {
        const int cur = kt & 1;
        if (kt < 31) {
            ra = *(const float4*)(Xa + (size_t)(kt + 1) * 8 * HW);
            rb = *(const float4*)(Wb + (kt + 1) * 8);
        }
#pragma unroll
        for (int k = 0; k < 8; k++) {
            ulonglong2 a01 = *(const ulonglong2*)(&As[cur][k][ty * 4]);
            ulonglong2 a23 = *(const ulonglong2*)(&As[cur][k][64 + ty * 4]);
            float4 bv0 = *(const float4*)(&Bs[cur][k][tx * 4]);
            float4 bv1 = *(const float4*)(&Bs[cur][k][64 + tx * 4]);
            unsigned long long av[4] = { a01.x, a01.y, a23.x, a23.y };
            unsigned long long bd[8];
            bd[0] = dup2(bv0.x); bd[1] = dup2(bv0.y);
            bd[2] = dup2(bv0.z); bd[3] = dup2(bv0.w);
            bd[4] = dup2(bv1.x); bd[5] = dup2(bv1.y);
            bd[6] = dup2(bv1.z); bd[7] = dup2(bv1.w);
#pragma unroll
            for (int i2 = 0; i2 < 4; i2++)
#pragma unroll
                for (int j = 0; j < 8; j++)
                    fma2(acc2[i2][j], av[i2], bd[j]);
        }

        // transpose side-output: x[kt*8 + c][p0+p] -> g_q[(p0+p)*CH + kt*8 + c]
        if (do_tr) {
            float4 v = make_float4(As[cur][t_c4 + 0][t_p],
                                   As[cur][t_c4 + 1][t_p],
                                   As[cur][t_c4 + 2][t_p],
                                   As[cur][t_c4 + 3][t_p]);
            *(float4*)(Q + (size_t)(p0 + t_p) * CH + kt * 8 + t_c4) = v;
        }

        if (kt < 31) {
            const int nxt = cur ^ 1;
            *(float4*)(&As[nxt][a_cr][a_p4]) = ra;
            Bs[nxt][b_c4 + 0][b_o] = rb.x;
            Bs[nxt][b_c4 + 1][b_o] = rb.y;
            Bs[nxt][b_c4 + 2][b_o] = rb.z;
            Bs[nxt][b_c4 + 3][b_o] = rb.w;
            __syncthreads();
        }
    }

#pragma unroll
    for (int i2 = 0; i2 < 4; i2++) {
        const int prow = p0 + ((i2 < 2) ? (ty * 4 + 2 * i2)
                                        : (64 + ty * 4 + 2 * (i2 - 2)));
        float lo[8], hi[8];
#pragma unroll
        for (int j = 0; j < 8; j++) {
            float2 t = unpk(acc2[i2][j]);
            lo[j] = t.x; hi[j] = t.y;
        }
        float* yl = Y + (size_t)prow * CH + o0;
        *(float4*)(yl + tx * 4)      = make_float4(lo[0], lo[1], lo[2], lo[3]);
        *(float4*)(yl + 64 + tx * 4) = make_float4(lo[4], lo[5], lo[6], lo[7]);
        float* yh = yl + CH;
        *(float4*)(yh + tx * 4)      = make_float4(hi[0], hi[1], hi[2], hi[3]);
        *(float4*)(yh + 64 + tx * 4) = make_float4(hi[4], hi[5], hi[6], hi[7]);
    }
}

// ---------------------------------------------------------------------------
// Kernel B: u = M x (pixel-major out).  Same FFMA2 tile, W = g_M.
// ---------------------------------------------------------------------------
__global__ __launch_bounds__(256) void gemm_u_kernel(const float* __restrict__ x)
{
    const int b  = blockIdx.z;
    const int p0 = blockIdx.x * 128;
    const int o0 = blockIdx.y * 128;

    const float* X = x + (size_t)b * CH * HW;
    float* Y = g_u + (size_t)b * HW * CH;

    __shared__ float As[2][8][128];
    __shared__ float Bs[2][8][128];

    const int tid = threadIdx.x;
    const int tx  = tid & 15;
    const int ty  = tid >> 4;

    const int a_cr = tid >> 5;
    const int a_p4 = (tid & 31) << 2;
    const int b_o  = tid >> 1;
    const int b_c4 = (tid & 1) << 2;

    const float* Xa = X + (size_t)a_cr * HW + p0 + a_p4;
    const float* Wb = g_M + (size_t)(o0 + b_o) * CH + b_c4;

    float4 ra = *(const float4*)Xa;
    float4 rb = *(const float4*)Wb;
    *(float4*)(&As[0][a_cr][a_p4]) = ra;
    Bs[0][b_c4 + 0][b_o] = rb.x;
    Bs[0][b_c4 + 1][b_o] = rb.y;
    Bs[0][b_c4 + 2][b_o] = rb.z;
    Bs[0][b_c4 + 3][b_o] = rb.w;
    __syncthreads();

    unsigned long long acc2[4][8];
#pragma unroll
    for (int i = 0; i < 4; i++)
#pragma unroll
        for (int j = 0; j < 8; j++) acc2[i][j] = 0ULL;

#pragma unroll 2
    for (int kt = 0; kt < 32; kt++) {
        const int cur = kt & 1;
        if (kt < 31) {
            ra = *(const float4*)(Xa + (size_t)(kt + 1) * 8 * HW);
            rb = *(const float4*)(Wb + (kt + 1) * 8);
        }
#pragma unroll
        for (int k = 0; k < 8; k++) {
            ulonglong2 a01 = *(const ulonglong2*)(&As[cur][k][ty * 4]);
            ulonglong2 a23 = *(const ulonglong2*)(&As[cur][k][64 + ty * 4]);
            float4 bv0 = *(const float4*)(&Bs[cur][k][tx * 4]);
            float4 bv1 = *(const float4*)(&Bs[cur][k][64 + tx * 4]);
            unsigned long long av[4] = { a01.x, a01.y, a23.x, a23.y };
            unsigned long long bd[8];
            bd[0] = dup2(bv0.x); bd[1] = dup2(bv0.y);
            bd[2] = dup2(bv0.z); bd[3] = dup2(bv0.w);
            bd[4] = dup2(bv1.x); bd[5] = dup2(bv1.y);
            bd[6] = dup2(bv1.z); bd[7] = dup2(bv1.w);
#pragma unroll
            for (int i2 = 0; i2 < 4; i2++)
#pragma unroll
                for (int j = 0; j < 8; j++)
                    fma2(acc2[i2][j], av[i2], bd[j]);
        }
        if (kt < 31) {
            const int nxt = cur ^ 1;
            *(float4*)(&As[nxt][a_cr][a_p4]) = ra;
            Bs[nxt][b_c4 + 0][b_o] = rb.x;
            Bs[nxt][b_c4 + 1][b_o] = rb.y;
            Bs[nxt][b_c4 + 2][b_o] = rb.z;
            Bs[nxt][b_c4 + 3][b_o] = rb.w;
            __syncthreads();
        }
    }

#pragma unroll
    for (int i2 = 0; i2 < 4; i2++) {
        const int prow = p0 + ((i2 < 2) ? (ty * 4 + 2 * i2)
                                        : (64 + ty * 4 + 2 * (i2 - 2)));
        float lo[8], hi[8];
#pragma unroll
        for (int j = 0; j < 8; j++) {
            float2 t = unpk(acc2[i2][j]);
            lo[j] = t.x; hi[j] = t.y;
        }
        float* yl = Y + (size_t)prow * CH + o0;
        *(float4*)(yl + tx * 4)      = make_float4(lo[0], lo[1], lo[2], lo[3]);
        *(float4*)(yl + 64 + tx * 4) = make_float4(lo[4], lo[5], lo[6], lo[7]);
        float* yh = yl + CH;
        *(float4*)(yh + tx * 4)      = make_float4(hi[0], hi[1], hi[2], hi[3]);
        *(float4*)(yh + 64 + tx * 4) = make_float4(hi[4], hi[5], hi[6], hi[7]);
    }
}

// ---------------------------------------------------------------------------
// Attention: block = (b, h, half-row of 32 px). 256 threads.  (R11 verbatim)
// cp.async 2-stage pipeline; compute/softmax/phase2 = proven R5 code.
// ---------------------------------------------------------------------------
#define WS_OFF   0
#define BUF0     1664
#define BUFSZ    (PXB*STR + X2ROWS*STR)     // 5960
#define X2_REL   (PXB*STR)                  // 640
#define OUTS_OFF BUF0
#define SMEM_FLOATS (1664 + 2*BUFSZ)        // 13584
#define NUNITS   (PXB*4 + X2ROWS*4)         // 1192 float4 staging units / chunk

__global__ __launch_bounds__(256) void attn_kernel(float* __restrict__ out)
{
    extern __shared__ float smem[];
    float* ws   = smem + WS_OFF;
    float* outS = smem + OUTS_OFF;

    const int blk  = blockIdx.x;          // b*128 + h*2 + half
    const int b    = blk >> 7;
    const int h    = (blk >> 1) & 63;
    const int half = blk & 1;
    const int px0  = half * PXB;
    const int tid  = threadIdx.x;

    const int px   = tid >> 3;            // 0..31
    const int part = tid & 7;             // 0..7

    const size_t bbase = (size_t)b * HW;
    const unsigned smem_u32 =
        (unsigned)__cvta_generic_to_shared(smem);

    // ---- staging plan: 5 float4 units per thread, computed once ----
    const float* gp[5];
    int so[5];                            // within-buffer float offset, -1 = none
#pragma unroll
    for (int it = 0; it < 5; it++) {
        int unit = tid + it * 256;
        gp[it] = 0; so[it] = -1;
        if (unit < PXB * 4) {
            int p  = unit >> 2;
            int c4 = (unit & 3) << 2;
            gp[it] = g_q + (bbase + (size_t)h * WID + px0 + p) * CH + c4;
            so[it] = p * STR + c4;
        } else if (unit < NUNITS) {
            int u   = unit - PXB * 4;
            int row = u >> 2;
            int c4  = (u & 3) << 2;
            int dh  = row / NCB;
            int col = row - dh * NCB;
            int hh  = h + dh - RAD;
            int gw  = px0 + col - RAD;
            so[it] = X2_REL + row * STR + c4;
            if (hh >= 0 && hh < HGT && gw >= 0 && gw < WID)
                gp[it] = g_u + (bbase + (size_t)hh * WID + gw) * CH + c4;
        }
    }

    // ---- per-thread logit rows (buffer-relative offsets) ----
    float acc[7];
    int   nbrow[7];
#pragma unroll
    for (int j = 0; j < 7; j++) {
        acc[j] = 0.f;
        int k  = part + 8 * j;
        int kk = (k < NK) ? k : 0;
        int dh = kk / 7, dw = kk - dh * 7;
        nbrow[j] = X2_REL + (dh * NCB + px + dw) * STR;
    }

    // ---- issue chunks 0 and 1 ----
#pragma unroll
    for (int pc = 0; pc < 2; pc++) {
        const unsigned base = smem_u32 + (BUF0 + pc * BUFSZ) * 4u;
#pragma unroll
        for (int it = 0; it < 5; it++) {
            if (so[it] >= 0) {
                const float* src = gp[it] ? (gp[it] + pc * CHUNK) : (const float*)g_q;
                cp_async16(base + so[it] * 4u, src, gp[it] ? 16u : 0u);
            }
        }
        CP_COMMIT();
    }

    for (int ch = 0; ch < CH / CHUNK; ch++) {
        if (ch == CH / CHUNK - 1) { CP_WAIT0(); } else { CP_WAIT1(); }
        __syncthreads();

        const float* bp  = smem + BUF0 + (ch & 1) * BUFSZ;
        const float* x1p = bp + px * STR;
#pragma unroll
        for (int c4 = 0; c4 < CHUNK; c4 += 4) {
            float4 qa = *(const float4*)(x1p + c4);
#pragma unroll
            for (int j = 0; j < 7; j++) {
                float4 kb = *(const float4*)(bp + nbrow[j] + c4);
                acc[j] = fmaf(qa.x, kb.x, acc[j]);
                acc[j] = fmaf(qa.y, kb.y, acc[j]);
                acc[j] = fmaf(qa.z, kb.z, acc[j]);
                acc[j] = fmaf(qa.w, kb.w, acc[j]);
            }
        }
        __syncthreads();

        if (ch + 2 < CH / CHUNK) {
            const int cco = (ch + 2) * CHUNK;
            const unsigned base = smem_u32 + (BUF0 + (ch & 1) * BUFSZ) * 4u;
#pragma unroll
            for (int it = 0; it < 5; it++) {
                if (so[it] >= 0) {
                    const float* src = gp[it] ? (gp[it] + cco) : (const float*)g_q;
                    cp_async16(base + so[it] * 4u, src, gp[it] ? 16u : 0u);
                }
            }
            CP_COMMIT();
        }
    }

    // ---- softmax across the 8-thread group owning pixel px ----
    float m = -1e30f;
#pragma unroll
    for (int j = 0; j < 7; j++)
        if (part + 8 * j < NK) m = fmaxf(m, acc[j]);
    m = fmaxf(m, __shfl_xor_sync(0xffffffffu, m, 1));
    m = fmaxf(m, __shfl_xor_sync(0xffffffffu, m, 2));
    m = fmaxf(m, __shfl_xor_sync(0xffffffffu, m, 4));

    float e[7];
    float s = 0.f;
#pragma unroll
    for (int j = 0; j < 7; j++) {
        int k = part + 8 * j;
        e[j] = (k < NK) ? __expf(acc[j] - m) : 0.f;
        s += e[j];
    }
    s += __shfl_xor_sync(0xffffffffu, s, 1);
    s += __shfl_xor_sync(0xffffffffu, s, 2);
    s += __shfl_xor_sync(0xffffffffu, s, 4);
    float inv = 1.f / s;
#pragma unroll
    for (int j = 0; j < 7; j++) {
        int k = part + 8 * j;
        if (k < NK) ws[px * WSTR + k] = e[j] * inv;
    }
    __syncthreads();

    // ---- Phase 2: thread = channel; two passes of 16 pixels ----
    const int c = tid;
#pragma unroll 1
    for (int hv = 0; hv < 2; hv++) {
        const int p0h = px0 + hv * 16;   // global first pixel of this pass
        const int pl0 = hv * 16;         // block-local first pixel

        float oacc[16];
#pragma unroll
        for (int i = 0; i < 16; i++) oacc[i] = 0.f;

        for (int dh = 0; dh < 7; dh++) {
            int hh = h + dh - RAD;
            if (hh < 0 || hh >= HGT) continue;          // uniform branch
            const float* vrow = g_v + (bbase + (size_t)hh * WID) * CH + c;
            const float* wsp  = ws + pl0 * WSTR + dh * 7;
#pragma unroll
            for (int wg = 0; wg < 22; wg++) {           // 16 + 6 neighborhood cols
                int gw = p0h + wg - RAD;
                float vv = (gw >= 0 && gw < WID) ? vrow[(size_t)gw * CH] : 0.f;
#pragma unroll
                for (int dw = 0; dw < 7; dw++) {
                    int pl = wg - dw;                   // compile-time per iter
                    if (pl >= 0 && pl < 16)
                        oacc[pl] = fmaf(wsp[pl * WSTR + dw], vv, oacc[pl]);
                }
            }
        }

        // transpose through smem for coalesced stores
#pragma unroll
        for (int i = 0; i < 16; i++) outS[c * STR + i] = oacc[i];
        __syncthreads();

#pragma unroll
        for (int r4 = 0; r4 < 4; r4++) {
            int idx = tid + r4 * 256;     // 0..1023 float4 units
            int cch = idx >> 2;
            int w4  = (idx & 3) << 2;
            float4 v = *(const float4*)(outS + cch * STR + w4);
            *(float4*)(out + ((size_t)(b * CH + cch) * HGT + h) * WID + p0h + w4) = v;
        }
        __syncthreads();
    }
}

// ---------------------------------------------------------------------------
extern "C" void kernel_launch(void* const* d_in, const int* in_sizes, int n_in,
                              void* d_out, int out_size)
{
    const float* x  = (const float*)d_in[0];
    const float* w1 = (const float*)d_in[1];
    const float* w2 = (const float*)d_in[2];
    const float* w3 = (const float*)d_in[3];
    float* out = (float*)d_out;
    (void)in_sizes; (void)n_in; (void)out_size;

    cudaFuncSetAttribute(attn_kernel,
                         cudaFuncAttributeMaxDynamicSharedMemorySize,
                         SMEM_FLOATS * (int)sizeof(float));

    gemm_v_mmul_kernel<<<272, 256>>>(x, w1, w2, w3);

    dim3 ugrid(HW / 128, CH / 128, BATCH);
    gemm_u_kernel<<<ugrid, 256>>>(x);

    attn_kernel<<<BATCH * HGT * 2, 256, SMEM_FLOATS * sizeof(float)>>>(out);
}